// round 14
// baseline (speedup 1.0000x reference)
#include <cuda_runtime.h>
#include <cuda_bf16.h>

// InverseLeakySoftplus: solve a*x + (1-a)*softplus(x) = y, a = 0.1+0.4*sigmoid(raw_alpha).
//
// R13 post-mortem: streaming cache hints neutral -> L2 policy exonerated.
// Main pinned at 46us / DRAM 58% across all coverage knobs. New ceiling
// theory: gstride-interleaved IPT batches put a warp's 8 outstanding loads
// 2.5MB apart -> every request opens a new DRAM row, ~60% HBM efficiency.
// R14: block-contiguous tiling — warp's 8 loads span 32KB contiguous
// (offsets i0 + j*TPB become compile-time immediates: LDG [R+0x1000*j],
// single IMAD.WIDE, hard front-batch). Table/bounds/grid frozen from R12.

#define NSEG  3200
#define YMINF (-16.0f)
#define H_F   0.01f
#define INVH  100.0f
#define TOFF  1600.0f          // -YMIN/h
#define TPB   256
#define IPT   8                // float4 per thread per grid-stride step
#define NBLOCKS 608            // 152 SMs x 4 blocks

__device__ float2 g_tab[NSEG];  // {x_k, x_{k+1}-x_k}
__device__ float  g_inva;

// ---------- table builder ----------
__device__ __forceinline__ float solve_knot(float y, float a, float oma, float inva)
{
    float x = (y > 0.0f) ? y : y * inva;
#pragma unroll
    for (int it = 0; it < 6; ++it) {
        float e  = __expf(-fabsf(x));
        float op = 1.0f + e;
        float sp = __logf(op) + fmaxf(x, 0.0f);
        float fx = fmaf(a, x, oma * sp);
        float num = (x >= 0.0f) ? fmaf(a, e, 1.0f) : (a + e);
        x -= __fdividef((fx - y) * op, num);
    }
    return x;
}

__global__ void build_table(const float* __restrict__ raw_alpha)
{
    int k = blockIdx.x * blockDim.x + threadIdx.x;
    float r    = __ldg(raw_alpha);
    float sig  = __fdividef(1.0f, 1.0f + __expf(-r));
    float a    = fmaf(0.4f, sig, 0.1f);
    float oma  = 1.0f - a;
    float inva = __fdividef(1.0f, a);
    if (k == 0) g_inva = inva;
    if (k < NSEG) {
        float y0 = YMINF + (float)k * H_F;
        float x0 = solve_knot(y0, a, oma, inva);
        float x1 = solve_knot(y0 + H_F, a, oma, inva);
        g_tab[k] = make_float2(x0, x1 - x0);
    }
}

// ---------- main: lerp, one LDS.64 per element, zero MUFU ----------
__device__ __forceinline__ float lerp_solve(float y, float inva,
                                            const float2* __restrict__ s_tab)
{
    float t = fmaf(y, INVH, TOFF);
    t = fminf(fmaxf(t, 0.0f), (float)NSEG - 0.001f);
    int   k  = (int)t;
    float fr = t - (float)k;
    float2 p = s_tab[k];
    float x  = fmaf(fr, p.y, p.x);
    x = (y >=  16.0f) ? y        : x;
    x = (y <= -16.0f) ? y * inva : x;
    return x;
}

__global__ void __launch_bounds__(TPB, 4)
inv_lsp_main(const float4* __restrict__ in, float4* __restrict__ out, int n4)
{
    __shared__ float2 s_tab[NSEG];
    for (int j = threadIdx.x; j < NSEG; j += TPB) s_tab[j] = g_tab[j];
    float inva = g_inva;
    __syncthreads();

    // Block-contiguous tiles: block b owns [b*TPB*IPT, (b+1)*TPB*IPT) each
    // outer step; within a tile, batch offsets are compile-time immediates.
    long long base = (long long)blockIdx.x * (TPB * IPT) + threadIdx.x;
    long long step = (long long)gridDim.x * (TPB * IPT);

    for (long long i0 = base; i0 < n4; i0 += step) {
        float4 v[IPT];
        int    ok[IPT];
#pragma unroll
        for (int j = 0; j < IPT; ++j) {          // front-batched, contiguous 32KB/warp
            long long i = i0 + j * TPB;
            ok[j] = (i < n4);
            if (ok[j]) v[j] = in[i];
        }
#pragma unroll
        for (int j = 0; j < IPT; ++j) {
            if (ok[j]) {
                float4 rr;
                rr.x = lerp_solve(v[j].x, inva, s_tab);
                rr.y = lerp_solve(v[j].y, inva, s_tab);
                rr.z = lerp_solve(v[j].z, inva, s_tab);
                rr.w = lerp_solve(v[j].w, inva, s_tab);
                out[i0 + j * TPB] = rr;
            }
        }
    }
}

// ---------- scalar tail (safety; unused when n % 4 == 0) ----------
__global__ void inv_lsp_scalar_tail(const float* __restrict__ in,
                                    float* __restrict__ out,
                                    int start, int n)
{
    int i = start + blockIdx.x * blockDim.x + threadIdx.x;
    if (i >= n) return;
    float inva = g_inva;
    float a    = __fdividef(1.0f, inva);
    float oma  = 1.0f - a;
    float y = in[i];
    float x = (y > 0.0f) ? y : y * inva;
#pragma unroll
    for (int it = 0; it < 8; ++it) {
        float e  = __expf(-fabsf(x));
        float op = 1.0f + e;
        float sp = __logf(op) + fmaxf(x, 0.0f);
        float fx = fmaf(a, x, oma * sp);
        float num = (x >= 0.0f) ? fmaf(a, e, 1.0f) : (a + e);
        x -= __fdividef((fx - y) * op, num);
    }
    out[i] = x;
}

extern "C" void kernel_launch(void* const* d_in, const int* in_sizes, int n_in,
                              void* d_out, int out_size)
{
    const float* in        = (const float*)d_in[0];
    const float* raw_alpha = (const float*)d_in[1];
    float* out             = (float*)d_out;
    int n = in_sizes[0];

    build_table<<<(NSEG + 127) / 128, 128>>>(raw_alpha);

    int n4 = n / 4;
    if (n4 > 0) {
        int blocks = NBLOCKS;
        long long needed = ((long long)n4 + TPB - 1) / TPB;
        if (needed < blocks) blocks = (int)needed;
        inv_lsp_main<<<blocks, TPB>>>((const float4*)in, (float4*)out, n4);
    }
    int rem = n - n4 * 4;
    if (rem > 0) {
        inv_lsp_scalar_tail<<<1, 256>>>(in, out, n4 * 4, n);
    }
}

// round 15
// speedup vs baseline: 1.0444x; 1.0444x over previous
#include <cuda_runtime.h>
#include <cuda_bf16.h>

// InverseLeakySoftplus: solve a*x + (1-a)*softplus(x) = y, a = 0.1+0.4*sigmoid(raw_alpha).
//
// R14 post-mortem: DRAM ~58% is the platform ceiling for this 50/50 R/W
// streaming mix (held across IPT, addressing, cache hints, occupancy).
// Harness ground truth favors IPT=4 (R7: 52.0 vs 55-57 for IPT=8).
// R15 consolidation: IPT=4, block-contiguous tiles of 1024 float4.
// n4 = 8,388,608 is divisible by 1024 -> predicate-FREE kernel (no ok[]
// regs, no bounds compares; offsets j*4096B are LDG immediates, hard
// front-batch). Guarded fallback kernel for non-divisible n (never used here).

#define NSEG  3200
#define YMINF (-16.0f)
#define H_F   0.01f
#define INVH  100.0f
#define TOFF  1600.0f          // -YMIN/h
#define TPB   256
#define IPT   4                // float4 per thread per tile
#define TILE  (TPB * IPT)      // 1024 float4 per block-tile
#define NBLOCKS 608            // 152 SMs x 4 blocks

__device__ float2 g_tab[NSEG];  // {x_k, x_{k+1}-x_k}
__device__ float  g_inva;

// ---------- table builder ----------
__device__ __forceinline__ float solve_knot(float y, float a, float oma, float inva)
{
    float x = (y > 0.0f) ? y : y * inva;
#pragma unroll
    for (int it = 0; it < 6; ++it) {
        float e  = __expf(-fabsf(x));
        float op = 1.0f + e;
        float sp = __logf(op) + fmaxf(x, 0.0f);
        float fx = fmaf(a, x, oma * sp);
        float num = (x >= 0.0f) ? fmaf(a, e, 1.0f) : (a + e);
        x -= __fdividef((fx - y) * op, num);
    }
    return x;
}

__global__ void build_table(const float* __restrict__ raw_alpha)
{
    int k = blockIdx.x * blockDim.x + threadIdx.x;
    float r    = __ldg(raw_alpha);
    float sig  = __fdividef(1.0f, 1.0f + __expf(-r));
    float a    = fmaf(0.4f, sig, 0.1f);
    float oma  = 1.0f - a;
    float inva = __fdividef(1.0f, a);
    if (k == 0) g_inva = inva;
    if (k < NSEG) {
        float y0 = YMINF + (float)k * H_F;
        float x0 = solve_knot(y0, a, oma, inva);
        float x1 = solve_knot(y0 + H_F, a, oma, inva);
        g_tab[k] = make_float2(x0, x1 - x0);
    }
}

// ---------- main: lerp, one LDS.64 per element, zero MUFU ----------
__device__ __forceinline__ float lerp_solve(float y, float inva,
                                            const float2* __restrict__ s_tab)
{
    float t = fmaf(y, INVH, TOFF);
    t = fminf(fmaxf(t, 0.0f), (float)NSEG - 0.001f);
    int   k  = (int)t;
    float fr = t - (float)k;
    float2 p = s_tab[k];
    float x  = fmaf(fr, p.y, p.x);
    x = (y >=  16.0f) ? y        : x;
    x = (y <= -16.0f) ? y * inva : x;
    return x;
}

// Predicate-free version: requires n4 % TILE == 0 (true for this problem).
__global__ void __launch_bounds__(TPB, 4)
inv_lsp_main_exact(const float4* __restrict__ in, float4* __restrict__ out, int n4)
{
    __shared__ float2 s_tab[NSEG];
    for (int j = threadIdx.x; j < NSEG; j += TPB) s_tab[j] = g_tab[j];
    float inva = g_inva;
    __syncthreads();

    long long base = (long long)blockIdx.x * TILE + threadIdx.x;
    long long step = (long long)gridDim.x * TILE;

    for (long long i0 = base; i0 < n4; i0 += step) {
        float4 v[IPT];
#pragma unroll
        for (int j = 0; j < IPT; ++j)            // unconditional front-batch,
            v[j] = in[i0 + j * TPB];             // offsets are 4KB immediates
#pragma unroll
        for (int j = 0; j < IPT; ++j) {
            float4 rr;
            rr.x = lerp_solve(v[j].x, inva, s_tab);
            rr.y = lerp_solve(v[j].y, inva, s_tab);
            rr.z = lerp_solve(v[j].z, inva, s_tab);
            rr.w = lerp_solve(v[j].w, inva, s_tab);
            out[i0 + j * TPB] = rr;
        }
    }
}

// Guarded fallback (general n4).
__global__ void __launch_bounds__(TPB, 4)
inv_lsp_main_guard(const float4* __restrict__ in, float4* __restrict__ out, int n4)
{
    __shared__ float2 s_tab[NSEG];
    for (int j = threadIdx.x; j < NSEG; j += TPB) s_tab[j] = g_tab[j];
    float inva = g_inva;
    __syncthreads();

    long long base = (long long)blockIdx.x * TILE + threadIdx.x;
    long long step = (long long)gridDim.x * TILE;

    for (long long i0 = base; i0 < n4; i0 += step) {
        float4 v[IPT];
        int    ok[IPT];
#pragma unroll
        for (int j = 0; j < IPT; ++j) {
            long long i = i0 + j * TPB;
            ok[j] = (i < n4);
            if (ok[j]) v[j] = in[i];
        }
#pragma unroll
        for (int j = 0; j < IPT; ++j) {
            if (ok[j]) {
                float4 rr;
                rr.x = lerp_solve(v[j].x, inva, s_tab);
                rr.y = lerp_solve(v[j].y, inva, s_tab);
                rr.z = lerp_solve(v[j].z, inva, s_tab);
                rr.w = lerp_solve(v[j].w, inva, s_tab);
                out[i0 + j * TPB] = rr;
            }
        }
    }
}

// ---------- scalar tail (safety; unused when n % 4 == 0) ----------
__global__ void inv_lsp_scalar_tail(const float* __restrict__ in,
                                    float* __restrict__ out,
                                    int start, int n)
{
    int i = start + blockIdx.x * blockDim.x + threadIdx.x;
    if (i >= n) return;
    float inva = g_inva;
    float a    = __fdividef(1.0f, inva);
    float oma  = 1.0f - a;
    float y = in[i];
    float x = (y > 0.0f) ? y : y * inva;
#pragma unroll
    for (int it = 0; it < 8; ++it) {
        float e  = __expf(-fabsf(x));
        float op = 1.0f + e;
        float sp = __logf(op) + fmaxf(x, 0.0f);
        float fx = fmaf(a, x, oma * sp);
        float num = (x >= 0.0f) ? fmaf(a, e, 1.0f) : (a + e);
        x -= __fdividef((fx - y) * op, num);
    }
    out[i] = x;
}

extern "C" void kernel_launch(void* const* d_in, const int* in_sizes, int n_in,
                              void* d_out, int out_size)
{
    const float* in        = (const float*)d_in[0];
    const float* raw_alpha = (const float*)d_in[1];
    float* out             = (float*)d_out;
    int n = in_sizes[0];

    build_table<<<(NSEG + 127) / 128, 128>>>(raw_alpha);

    int n4 = n / 4;
    if (n4 > 0) {
        int blocks = NBLOCKS;
        long long needed = ((long long)n4 + TPB - 1) / TPB;
        if (needed < blocks) blocks = (int)needed;
        if ((n4 % TILE) == 0)
            inv_lsp_main_exact<<<blocks, TPB>>>((const float4*)in, (float4*)out, n4);
        else
            inv_lsp_main_guard<<<blocks, TPB>>>((const float4*)in, (float4*)out, n4);
    }
    int rem = n - n4 * 4;
    if (rem > 0) {
        inv_lsp_scalar_tail<<<1, 256>>>(in, out, n4 * 4, n);
    }
}